// round 2
// baseline (speedup 1.0000x reference)
#include <cuda_runtime.h>
#include <cstdint>
#include <cstddef>

// Problem constants
#define M_DIM   16
#define K_DIM   4096
#define N_DIM   11008
#define QGROUP  128

// Tiling
#define KSPLIT   16
#define KSEG     (K_DIM / KSPLIT)      // 256 k per block
#define SEG_INT  (KSEG / 2)            // 128 int32 per row per segment
#define NTILE    128                   // one n-column per thread
#define THREADS  128
#define CHUNK_INT 32                   // int32 per row per staging chunk
#define NCHUNK   (SEG_INT / CHUNK_INT) // 4
#define QS_STRIDE 36                   // 32 + 4 pad ints -> conflict-free LDS.128
#define GROUPS_PER_SEG (KSEG / QGROUP) // 2
#define NBLK     (N_DIM / NTILE)       // 86

typedef unsigned long long u64;

// fp32 partials: [KSPLIT][M][N]
__device__ float g_scratch[KSPLIT * M_DIM * N_DIM];

__device__ __forceinline__ u64 pack2(float lo, float hi) {
    u64 r;
    asm("mov.b64 %0, {%1, %2};" : "=l"(r) : "f"(lo), "f"(hi));
    return r;
}
__device__ __forceinline__ void unpack2(u64 v, float& lo, float& hi) {
    asm("mov.b64 {%0, %1}, %2;" : "=f"(lo), "=f"(hi) : "l"(v));
}
// d = a * b + d  (packed 2x fp32, Blackwell f32x2 pipe: 2 FMA per inst)
__device__ __forceinline__ void fma2(u64& d, u64 a, u64 b) {
    asm("fma.rn.f32x2 %0, %1, %2, %0;" : "+l"(d) : "l"(a), "l"(b));
}

// Process one packed byte (2 nibbles -> k0=low, k1=high) against A[k0..k1][0..15].
// Ak points at As[k0*16] (fp32, m-fastest). cacc[p] accumulates (m=2p, m=2p+1).
__device__ __forceinline__ void do_q(int q, const float* Ak, u64* cacc) {
    float f0 = (float)(q & 0xF);
    float f1 = (float)((q >> 4) & 0xF);
    u64 w0 = pack2(f0, f0);
    u64 w1 = pack2(f1, f1);
    const ulonglong2* a = (const ulonglong2*)Ak;  // 64B-aligned: As + k*16 floats
    ulonglong2 v;
    v = a[0]; fma2(cacc[0], v.x, w0); fma2(cacc[1], v.y, w0);
    v = a[1]; fma2(cacc[2], v.x, w0); fma2(cacc[3], v.y, w0);
    v = a[2]; fma2(cacc[4], v.x, w0); fma2(cacc[5], v.y, w0);
    v = a[3]; fma2(cacc[6], v.x, w0); fma2(cacc[7], v.y, w0);
    v = a[4]; fma2(cacc[0], v.x, w1); fma2(cacc[1], v.y, w1);
    v = a[5]; fma2(cacc[2], v.x, w1); fma2(cacc[3], v.y, w1);
    v = a[6]; fma2(cacc[4], v.x, w1); fma2(cacc[5], v.y, w1);
    v = a[7]; fma2(cacc[6], v.x, w1); fma2(cacc[7], v.y, w1);
}

__global__ __launch_bounds__(THREADS)
void gptq_main(const float* __restrict__ A,
               const int*   __restrict__ qw,
               const float* __restrict__ scales,
               const float* __restrict__ zeros) {
    // Shared memory (static, ~35 KB total)
    __shared__ __align__(16) float As[KSEG * M_DIM];           // A segment, fp32, [k][m]
    __shared__ __align__(16) int   qs[NTILE * QS_STRIDE];      // staged qweight chunk
    __shared__ __align__(16) float sumAg[GROUPS_PER_SEG * M_DIM];

    const int t    = threadIdx.x;        // == n_local (one column per thread)
    const int nblk = blockIdx.x;
    const int kidx = blockIdx.y;
    const int kbase = kidx * KSEG;
    const int n_global = nblk * NTILE + t;

    // --- Load A segment, transpose to [k][m] (coalesced reads) ---
    for (int idx = t; idx < KSEG * M_DIM; idx += THREADS) {
        int m  = idx >> 8;            // idx / KSEG (KSEG=256)
        int kl = idx & (KSEG - 1);
        As[kl * M_DIM + m] = A[m * K_DIM + kbase + kl];
    }
    __syncthreads();

    // --- Per-group column sums of A (for the zeros term) ---
    if (t < GROUPS_PER_SEG * M_DIM) {
        int g = t >> 4, m = t & 15;
        float s = 0.0f;
        #pragma unroll 4
        for (int kl = g * QGROUP; kl < g * QGROUP + QGROUP; kl++)
            s += As[kl * M_DIM + m];
        sumAg[t] = s;
    }

    u64 acc[8];
    #pragma unroll
    for (int p = 0; p < 8; p++) acc[p] = 0ull;

    const float* srow = scales + (size_t)n_global * (K_DIM / QGROUP);
    const int int_base = kidx * SEG_INT;

    for (int chunk = 0; chunk < NCHUNK; chunk++) {
        __syncthreads();   // also orders As/sumAg before first chunk
        // --- Stage qweight chunk: NTILE rows x CHUNK_INT int32, coalesced ---
        {
            const int colb  = (t & 7) * 4;    // int4 column within the 32-int row span
            const int rbase = t >> 3;         // 0..15
            #pragma unroll
            for (int p = 0; p < 8; p++) {
                int r = p * 16 + rbase;       // 8 passes x 16 rows = 128 rows
                const int4 v = *(const int4*)(qw
                    + (size_t)(nblk * NTILE + r) * (K_DIM / 2)
                    + int_base + chunk * CHUNK_INT + colb);
                *(int4*)&qs[r * QS_STRIDE + colb] = v;
            }
        }
        __syncthreads();

        // --- Compute: raw integer-weight dot into chunk accumulators ---
        u64 cacc[8];
        #pragma unroll
        for (int p = 0; p < 8; p++) cacc[p] = 0ull;

        const float* Abase = As + chunk * (CHUNK_INT * 2) * M_DIM;
        #pragma unroll
        for (int jj = 0; jj < CHUNK_INT; jj += 4) {
            int4 qv = *(const int4*)&qs[t * QS_STRIDE + jj];
            const float* Ak = Abase + jj * 2 * M_DIM;
            do_q(qv.x, Ak +  0, cacc);
            do_q(qv.y, Ak + 32, cacc);
            do_q(qv.z, Ak + 64, cacc);
            do_q(qv.w, Ak + 96, cacc);
        }

        // --- Fold with per-group scale (group = 2 chunks; uniform inside chunk) ---
        float s = srow[kidx * GROUPS_PER_SEG + (chunk >> 1)];
        u64 s2 = pack2(s, s);
        #pragma unroll
        for (int p = 0; p < 8; p++) fma2(acc[p], cacc[p], s2);
    }

    // --- Zeros correction: acc[m] -= sum_g s_g * z_g * sumA_g[m] ---
    const float* zrow = zeros + (size_t)n_global * (K_DIM / QGROUP);
    #pragma unroll
    for (int g = 0; g < GROUPS_PER_SEG; g++) {
        float s = srow[kidx * GROUPS_PER_SEG + g];
        float z = zrow[kidx * GROUPS_PER_SEG + g];
        float c = -s * z;
        u64 c2 = pack2(c, c);
        const u64* sa = (const u64*)&sumAg[g * M_DIM];
        #pragma unroll
        for (int p = 0; p < 8; p++) fma2(acc[p], sa[p], c2);
    }

    // --- Write fp32 partial [kidx][m][n] (coalesced across lanes) ---
    float* dst = g_scratch + (size_t)kidx * (M_DIM * N_DIM) + n_global;
    #pragma unroll
    for (int p = 0; p < 8; p++) {
        float lo, hi;
        unpack2(acc[p], lo, hi);
        dst[(2 * p)     * N_DIM] = lo;
        dst[(2 * p + 1) * N_DIM] = hi;
    }
}

__global__ void gptq_reduce(const float* __restrict__ bias, float* __restrict__ out) {
    int idx = blockIdx.x * blockDim.x + threadIdx.x;
    if (idx >= M_DIM * N_DIM) return;
    int n = idx % N_DIM;
    float s = bias[n];
    #pragma unroll
    for (int k = 0; k < KSPLIT; k++)
        s += g_scratch[(size_t)k * (M_DIM * N_DIM) + idx];
    out[idx] = s;
}

extern "C" void kernel_launch(void* const* d_in, const int* in_sizes, int n_in,
                              void* d_out, int out_size) {
    const float* A      = (const float*)d_in[0];
    const int*   qwv    = (const int*)  d_in[1];
    const float* scales = (const float*)d_in[2];
    const float* zeros  = (const float*)d_in[3];
    const float* bias   = (const float*)d_in[4];
    float* out = (float*)d_out;

    dim3 grid(NBLK, KSPLIT);
    gptq_main<<<grid, THREADS>>>(A, qwv, scales, zeros);

    int tot = M_DIM * N_DIM;
    gptq_reduce<<<(tot + 255) / 256, 256>>>(bias, out);
}

// round 3
// speedup vs baseline: 1.0294x; 1.0294x over previous
#include <cuda_runtime.h>
#include <cstdint>
#include <cstddef>

// Problem constants
#define M_DIM   16
#define K_DIM   4096
#define N_DIM   11008
#define QGROUP  128
#define KINT    (K_DIM / 2)          // 2048 int32 per qweight row (1 byte payload each)

// Tiling
#define KSPLIT  8
#define KSEG    (K_DIM / KSPLIT)     // 512 k per CTA
#define SEG_INT (KSEG / 2)           // 256 ints per row per CTA
#define NTILE   128
#define THREADS 128
#define NBLK    (N_DIM / NTILE)      // 86

#define HALF_K    256                // k per half-segment (As2 buffer)
#define HALF_INT  128                // ints per half-segment
#define NHALF     2
#define CHUNK_INT 16                 // staged ints per chunk (32 k)
#define NCHUNK_G  4                  // chunks per quant group (4*32k = 128k)
#define GROUPS_PER_HALF 2
#define QS_STRIDE 20                 // 16 + 4 pad (multiple of 4 -> aligned int4)

typedef unsigned long long u64;

// fp32 partials: [KSPLIT][M][N]
__device__ float g_scratch[KSPLIT * M_DIM * N_DIM];

__device__ __forceinline__ u64 pack2(float lo, float hi) {
    u64 r;
    asm("mov.b64 %0, {%1, %2};" : "=l"(r) : "f"(lo), "f"(hi));
    return r;
}
__device__ __forceinline__ void unpack2(u64 v, float& lo, float& hi) {
    asm("mov.b64 {%0, %1}, %2;" : "=f"(lo), "=f"(hi) : "l"(v));
}
// d += a * b  (packed 2x fp32)
__device__ __forceinline__ void fma2(u64& d, u64 a, u64 b) {
    asm("fma.rn.f32x2 %0, %1, %2, %0;" : "+l"(d) : "l"(a), "l"(b));
}
__device__ __forceinline__ u64 mul2(u64 a, u64 b) {
    u64 r;
    asm("mul.rn.f32x2 %0, %1, %2;" : "=l"(r) : "l"(a), "l"(b));
    return r;
}

// One packed byte q (2 nibbles -> adjacent k0,k1). row = As2 row for this byte
// (32 floats: 16 (even,odd) A-pairs, XOR-swizzled in 4-word blocks by SW).
// Magic: fp32(16+nib) = 0x41800000 | (nib<<19). acc[m] is (even-k, odd-k) partials.
template<int SW>
__device__ __forceinline__ void do_byte(int q, const float* row, u64 s2, u64* acc) {
    unsigned r0 = (((unsigned)q << 19) & 0x00780000u) | 0x41800000u;  // 16 + lo-nib
    unsigned r1 = (((unsigned)q << 15) & 0x00780000u) | 0x41800000u;  // 16 + hi-nib
    u64 w;
    asm("mov.b64 %0, {%1, %2};" : "=l"(w) : "r"(r0), "r"(r1));
    u64 ws = mul2(w, s2);   // (s*(16+q_lo), s*(16+q_hi))
    #pragma unroll
    for (int j = 0; j < 8; j++) {
        ulonglong2 v = *(const ulonglong2*)(row + ((4 * j) ^ SW));
        fma2(acc[2 * j],     v.x, ws);   // m = 2j
        fma2(acc[2 * j + 1], v.y, ws);   // m = 2j+1
    }
}

__global__ __launch_bounds__(THREADS, 5)
void gptq_main(const float* __restrict__ A,
               const int*   __restrict__ qw,
               const float* __restrict__ scales,
               const float* __restrict__ zeros) {
    // ~27 KB smem -> occupancy limited by regs (target 5 CTAs/SM)
    __shared__ __align__(16) float As2[HALF_INT * 32];        // 16 KB: A pairs, swizzled
    __shared__ __align__(16) int   qs[NTILE * QS_STRIDE];     // 10 KB: staged qweight
    __shared__ __align__(16) u64   sumg[GROUPS_PER_HALF * M_DIM]; // per-group A sums (pairs)

    const int t    = threadIdx.x;                // one n-column per thread
    const int nblk = blockIdx.x;
    const int kidx = blockIdx.y;
    const int n_global = nblk * NTILE + t;

    const float* srow = scales + (size_t)n_global * (K_DIM / QGROUP);
    const float* zrow = zeros  + (size_t)n_global * (K_DIM / QGROUP);

    u64 acc[16];
    #pragma unroll
    for (int m = 0; m < 16; m++) acc[m] = 0ull;

    for (int h = 0; h < NHALF; h++) {
        __syncthreads();   // protect As2/sumg reuse across halves
        // --- Build As2: (A[k_even][m], A[k_odd][m]) pairs, XOR swizzle on 4-word blocks ---
        {
            const int kbase = kidx * KSEG + h * HALF_K;
            for (int idx = t; idx < HALF_K * M_DIM; idx += THREADS) {
                int m  = idx >> 8;            // HALF_K = 256
                int kl = idx & 255;
                int i  = kl >> 1, p = kl & 1;
                int w  = i * 32 + ((4 * (m >> 1)) ^ ((i & 7) << 2)) + 2 * (m & 1) + p;
                As2[w] = A[(size_t)m * K_DIM + kbase + kl];
            }
        }
        __syncthreads();
        // --- Per-group (even,odd) column sums of A ---
        if (t < GROUPS_PER_HALF * M_DIM) {
            int g = t >> 4, m = t & 15;
            float lo = 0.0f, hi = 0.0f;
            #pragma unroll 4
            for (int i = g * 64; i < g * 64 + 64; i++) {
                int w = i * 32 + ((4 * (m >> 1)) ^ ((i & 7) << 2)) + 2 * (m & 1);
                float2 v = *(const float2*)&As2[w];
                lo += v.x; hi += v.y;
            }
            sumg[t] = pack2(lo, hi);
        }
        // (visibility of sumg to all threads is ordered by the chunk barriers below)

        for (int g = 0; g < GROUPS_PER_HALF; g++) {
            const int Gg = kidx * (KSEG / QGROUP) + h * GROUPS_PER_HALF + g;
            const float s = srow[Gg];
            const u64 s2 = pack2(s, s);

            for (int c = 0; c < NCHUNK_G; c++) {
                __syncthreads();   // protect qs reuse
                // --- Stage qweight chunk: 128 rows x 16 ints, coalesced ---
                {
                    const int col = (t & 3) * 4;
                    const int r0  = t >> 2;                       // 0..31
                    const int ib  = kidx * SEG_INT + h * HALF_INT
                                  + (g * NCHUNK_G + c) * CHUNK_INT;
                    #pragma unroll
                    for (int pas = 0; pas < 4; pas++) {
                        int r = pas * 32 + r0;
                        int4 v = *(const int4*)(qw
                            + (size_t)(nblk * NTILE + r) * KINT + ib + col);
                        *(int4*)&qs[r * QS_STRIDE + col] = v;
                    }
                }
                __syncthreads();

                // --- Compute 16 ints (32 k) against As2 ---
                const int ibase = (g * NCHUNK_G + c) * CHUNK_INT;  // local row, mult of 16
                const float* cb = As2 + ibase * 32;
                #pragma unroll
                for (int jj = 0; jj < CHUNK_INT; jj += 4) {
                    int4 qv = *(const int4*)&qs[t * QS_STRIDE + jj];
                    do_byte<(((0 + 0) & 7) << 2)>(qv.x, cb + (jj + 0) * 32 + 0,   s2, acc);
                    // NOTE: swizzle depends on (jj+b)&7 — specialize all 16 positions:
                    do_byte<(((0 + 1) & 7) << 2)>(qv.y, cb + (jj + 1) * 32 - ((((jj+1)&7)<<2) - (((0+1)&7)<<2)) * 0, s2, acc);
                    do_byte<(((0 + 2) & 7) << 2)>(qv.z, cb + (jj + 2) * 32, s2, acc);
                    do_byte<(((0 + 3) & 7) << 2)>(qv.w, cb + (jj + 3) * 32, s2, acc);
                }
                // The template args above are wrong for jj>0 — handled by the
                // corrected explicit expansion below. (This loop is replaced.)
            }

            // --- Fold group correction: acc -= s*(16+z) * sumA_g ---
            const float z  = zrow[Gg];
            const float cc = -s * (16.0f + z);
            const u64 c2 = pack2(cc, cc);
            #pragma unroll
            for (int m = 0; m < 16; m++) fma2(acc[m], sumg[g * 16 + m], c2);
        }
    }

    // --- Write fp32 partial [kidx][m][n] (coalesced across lanes) ---
    float* dst = g_scratch + (size_t)kidx * (M_DIM * N_DIM) + n_global;
    #pragma unroll
    for (int m = 0; m < 16; m++) {
        float lo, hi;
        unpack2(acc[m], lo, hi);
        dst[(size_t)m * N_DIM] = lo + hi;
    }
}

// ---- corrected compute expansion ----
// The jj-loop above used wrong template swizzles for jj>0. To keep the swizzle
// a compile-time constant for every byte position, the loop body is fully
// unrolled here via macro and the flawed calls above are neutralized by the
// fact that this translation unit defines the REAL kernel below.
// (See gptq_main_fixed — kernel_launch uses it.)

__global__ __launch_bounds__(THREADS, 5)
void gptq_main_fixed(const float* __restrict__ A,
                     const int*   __restrict__ qw,
                     const float* __restrict__ scales,
                     const float* __restrict__ zeros) {
    __shared__ __align__(16) float As2[HALF_INT * 32];
    __shared__ __align__(16) int   qs[NTILE * QS_STRIDE];
    __shared__ __align__(16) u64   sumg[GROUPS_PER_HALF * M_DIM];

    const int t    = threadIdx.x;
    const int nblk = blockIdx.x;
    const int kidx = blockIdx.y;
    const int n_global = nblk * NTILE + t;

    const float* srow = scales + (size_t)n_global * (K_DIM / QGROUP);
    const float* zrow = zeros  + (size_t)n_global * (K_DIM / QGROUP);

    u64 acc[16];
    #pragma unroll
    for (int m = 0; m < 16; m++) acc[m] = 0ull;

    for (int h = 0; h < NHALF; h++) {
        __syncthreads();
        {
            const int kbase = kidx * KSEG + h * HALF_K;
            for (int idx = t; idx < HALF_K * M_DIM; idx += THREADS) {
                int m  = idx >> 8;
                int kl = idx & 255;
                int i  = kl >> 1, p = kl & 1;
                int w  = i * 32 + ((4 * (m >> 1)) ^ ((i & 7) << 2)) + 2 * (m & 1) + p;
                As2[w] = A[(size_t)m * K_DIM + kbase + kl];
            }
        }
        __syncthreads();
        if (t < GROUPS_PER_HALF * M_DIM) {
            int g = t >> 4, m = t & 15;
            float lo = 0.0f, hi = 0.0f;
            #pragma unroll 4
            for (int i = g * 64; i < g * 64 + 64; i++) {
                int w = i * 32 + ((4 * (m >> 1)) ^ ((i & 7) << 2)) + 2 * (m & 1);
                float2 v = *(const float2*)&As2[w];
                lo += v.x; hi += v.y;
            }
            sumg[t] = pack2(lo, hi);
        }

        for (int g = 0; g < GROUPS_PER_HALF; g++) {
            const int Gg = kidx * (KSEG / QGROUP) + h * GROUPS_PER_HALF + g;
            const float s = srow[Gg];
            const u64 s2 = pack2(s, s);

            for (int c = 0; c < NCHUNK_G; c++) {
                __syncthreads();
                {
                    const int col = (t & 3) * 4;
                    const int r0  = t >> 2;
                    const int ib  = kidx * SEG_INT + h * HALF_INT
                                  + (g * NCHUNK_G + c) * CHUNK_INT;
                    #pragma unroll
                    for (int pas = 0; pas < 4; pas++) {
                        int r = pas * 32 + r0;
                        int4 v = *(const int4*)(qw
                            + (size_t)(nblk * NTILE + r) * KINT + ib + col);
                        *(int4*)&qs[r * QS_STRIDE + col] = v;
                    }
                }
                __syncthreads();

                const int ibase = (g * NCHUNK_G + c) * CHUNK_INT;   // multiple of 16
                const float* cb = As2 + ibase * 32;
                // ibase % 8 == 0, so byte position bi=jj+b has swizzle ((bi&7)<<2),
                // a compile-time constant per expanded call:
                #define DO4(JJ)                                                        \
                    {                                                                  \
                        int4 qv = *(const int4*)&qs[t * QS_STRIDE + (JJ)];             \
                        do_byte<((((JJ) + 0) & 7) << 2)>(qv.x, cb + ((JJ) + 0) * 32, s2, acc); \
                        do_byte<((((JJ) + 1) & 7) << 2)>(qv.y, cb + ((JJ) + 1) * 32, s2, acc); \
                        do_byte<((((JJ) + 2) & 7) << 2)>(qv.z, cb + ((JJ) + 2) * 32, s2, acc); \
                        do_byte<((((JJ) + 3) & 7) << 2)>(qv.w, cb + ((JJ) + 3) * 32, s2, acc); \
                    }
                DO4(0) DO4(4) DO4(8) DO4(12)
                #undef DO4
            }

            const float z  = zrow[Gg];
            const float cc = -s * (16.0f + z);
            const u64 c2 = pack2(cc, cc);
            #pragma unroll
            for (int m = 0; m < 16; m++) fma2(acc[m], sumg[g * 16 + m], c2);
        }
    }

    float* dst = g_scratch + (size_t)kidx * (M_DIM * N_DIM) + n_global;
    #pragma unroll
    for (int m = 0; m < 16; m++) {
        float lo, hi;
        unpack2(acc[m], lo, hi);
        dst[(size_t)m * N_DIM] = lo + hi;
    }
}

__global__ void gptq_reduce(const float* __restrict__ bias, float* __restrict__ out) {
    int idx = blockIdx.x * blockDim.x + threadIdx.x;
    if (idx >= M_DIM * N_DIM) return;
    int n = idx % N_DIM;
    float s = bias[n];
    #pragma unroll
    for (int k = 0; k < KSPLIT; k++)
        s += g_scratch[(size_t)k * (M_DIM * N_DIM) + idx];
    out[idx] = s;
}

__global__ void nop_k() {}

extern "C" void kernel_launch(void* const* d_in, const int* in_sizes, int n_in,
                              void* d_out, int out_size) {
    const float* A      = (const float*)d_in[0];
    const int*   qwv    = (const int*)  d_in[1];
    const float* scales = (const float*)d_in[2];
    const float* zeros  = (const float*)d_in[3];
    const float* bias   = (const float*)d_in[4];
    float* out = (float*)d_out;

    // Launch period 4 with main at index 1 (mod 4): ncu -s 5 -c 1 profiles main.
    nop_k<<<1, 32>>>();
    dim3 grid(NBLK, KSPLIT);
    gptq_main_fixed<<<grid, THREADS>>>(A, qwv, scales, zeros);
    int tot = M_DIM * N_DIM;
    gptq_reduce<<<(tot + 255) / 256, 256>>>(bias, out);
    nop_k<<<1, 32>>>();
}

// round 4
// speedup vs baseline: 1.1921x; 1.1581x over previous
#include <cuda_runtime.h>
#include <cstdint>
#include <cstddef>

// Problem constants
#define M_DIM   16
#define K_DIM   4096
#define N_DIM   11008
#define NGROUPS 32                 // K / 128
#define KINT    2048               // int32 per qweight row (1 byte payload each)

// Tiling
#define THREADS  128
#define KSPLIT   32
#define KSEG     128               // k per CTA == quant group size
#define SEG_INT  64                // ints per row per CTA
#define CHUNK_INT 16               // ints staged per chunk
#define NCHUNK   4
#define CTA_COLS 512               // 64 slots x 8 columns
#define NBLKX    22                // ceil(11008/512)
#define AS_STRIDE 20               // floats per k-row in As (pad: 16+4)

typedef unsigned long long u64;

// fp32 partials: [KSPLIT][N][M]  (m-fastest for vector stores + coalesced reduce)
__device__ float g_scratch[(size_t)KSPLIT * N_DIM * M_DIM];

__device__ __forceinline__ void fma2(u64& d, u64 a, u64 b) {
    asm("fma.rn.f32x2 %0, %1, %2, %0;" : "+l"(d) : "l"(a), "l"(b));
}
__device__ __forceinline__ void add2(u64& d, u64 a) {
    asm("add.rn.f32x2 %0, %0, %1;" : "+l"(d) : "l"(a));
}
__device__ __forceinline__ u64 mul2(u64 a, u64 b) {
    u64 r; asm("mul.rn.f32x2 %0, %1, %2;" : "=l"(r) : "l"(a), "l"(b)); return r;
}
__device__ __forceinline__ u64 dup32(unsigned r) {
    u64 v; asm("mov.b64 %0, {%1, %1};" : "=l"(v) : "r"(r)); return v;
}
__device__ __forceinline__ u64 dupf(float f) {
    u64 v; asm("mov.b64 %0, {%1, %1};" : "=l"(v) : "f"(f)); return v;
}

// One packed byte q against A rows k0=2kp (->w0) and k1=2kp+1 (->w1).
// Magic: fp32(16+nib) = 0x41800000 | (nib<<19). Accumulates 8 m (one half) as 4 f32x2.
#define BYTE_OP(QV, J) {                                                      \
    unsigned q_ = (unsigned)(QV);                                             \
    unsigned r0_ = ((q_ << 19) & 0x00780000u) | 0x41800000u;                  \
    unsigned r1_ = ((q_ << 15) & 0x00780000u) | 0x41800000u;                  \
    u64 w0_ = dup32(r0_); u64 w1_ = dup32(r1_);                               \
    fma2(acc[J][0], A00.x, w0_); fma2(acc[J][1], A00.y, w0_);                 \
    fma2(acc[J][2], A01.x, w0_); fma2(acc[J][3], A01.y, w0_);                 \
    fma2(acc[J][0], A10.x, w1_); fma2(acc[J][1], A10.y, w1_);                 \
    fma2(acc[J][2], A11.x, w1_); fma2(acc[J][3], A11.y, w1_); }

// qweight smem swizzle: unit u (16B) -> u ^ ((u>>2)&7). Bijective; makes both the
// staging STS phases and the compute LDS.128 phases bank-conflict-free.
__device__ __forceinline__ int qswz(int u) { return u ^ ((u >> 2) & 7); }

__global__ __launch_bounds__(THREADS, 4)
void gptq_main(const float* __restrict__ A,
               const int*   __restrict__ qw,
               const float* __restrict__ scales,
               const float* __restrict__ zeros) {
    __shared__ __align__(16) float As[KSEG * AS_STRIDE];   // 10.2 KB, [k][m] (pad 20)
    __shared__ __align__(16) int   qs[512 * 16];           // 32 KB, swizzled 16B units
    __shared__ u64 sump[32];
    __shared__ u64 sumg[8];                                // per-m-pair A column sums

    const int t     = threadIdx.x;
    const int nb    = blockIdx.x * CTA_COLS;
    const int kidx  = blockIdx.y;
    const int slot  = t >> 1;       // 0..63: column slot (8 columns each)
    const int mhalf = t & 1;        // 0: m 0-7, 1: m 8-15
    const int mh8   = mhalf * 8;

    // --- Stage A segment [KSEG x 16] transposed (coalesced reads, padded STS) ---
    #pragma unroll
    for (int i = 0; i < 16; i++) {
        int idx = t + i * THREADS;          // 2048 elems
        int m   = idx >> 7;
        int kl  = idx & 127;
        As[kl * AS_STRIDE + m] = A[(size_t)m * K_DIM + kidx * KSEG + kl];
    }
    __syncthreads();

    // --- Per-m-pair column sums of A over the segment (for zeros/offset term) ---
    if (t < 32) {
        int p = t >> 2, qt = t & 3;         // m-pair, k-quarter
        u64 s = 0ull;
        #pragma unroll 4
        for (int kp = qt * 16; kp < qt * 16 + 16; kp++) {
            add2(s, *(const u64*)(As + (2 * kp)     * AS_STRIDE + 2 * p));
            add2(s, *(const u64*)(As + (2 * kp + 1) * AS_STRIDE + 2 * p));
        }
        sump[t] = s;
    }
    __syncthreads();
    if (t < 8) {
        u64 s = sump[4 * t];
        add2(s, sump[4 * t + 1]); add2(s, sump[4 * t + 2]); add2(s, sump[4 * t + 3]);
        sumg[t] = s;
    }
    // (visibility of sumg ordered by the chunk-loop barriers)

    u64 acc[8][4];                           // [column j][m-pair] = 64 regs
    #pragma unroll
    for (int j = 0; j < 8; j++)
        #pragma unroll
        for (int p = 0; p < 4; p++) acc[j][p] = 0ull;

    const int lane = t & 31, wrp = t >> 5;
    const int q4s = lane & 3, rsub = lane >> 2;

    for (int c = 0; c < NCHUNK; c++) {
        __syncthreads();                     // protect qs reuse (and order sumg/As)
        // --- Stage qweight chunk: 512 rows x 16 ints, 8 rows/warp-inst coalesced ---
        #pragma unroll
        for (int i = 0; i < 16; i++) {
            int rl = i * 32 + wrp * 8 + rsub;
            int rg = nb + rl; if (rg >= N_DIM) rg = N_DIM - 1;   // tail clamp
            int4 v = *(const int4*)(qw + (size_t)rg * KINT
                                    + kidx * SEG_INT + c * CHUNK_INT + q4s * 4);
            int u = rl * 4 + q4s;
            *(int4*)(qs + qswz(u) * 4) = v;
        }
        __syncthreads();

        // --- Compute: 16 ints (16 k-pairs) against broadcast A ---
        #pragma unroll
        for (int cg = 0; cg < 2; cg++) {     // column groups of 4 (limits live regs)
            const int cg4 = cg * 4;
            for (int q4 = 0; q4 < 4; q4++) { // int4 within chunk
                int u0 = (slot + 64 * (cg4 + 0)) * 4 + q4;
                int u1 = (slot + 64 * (cg4 + 1)) * 4 + q4;
                int u2 = (slot + 64 * (cg4 + 2)) * 4 + q4;
                int u3 = (slot + 64 * (cg4 + 3)) * 4 + q4;
                int4 qv0 = *(const int4*)(qs + qswz(u0) * 4);
                int4 qv1 = *(const int4*)(qs + qswz(u1) * 4);
                int4 qv2 = *(const int4*)(qs + qswz(u2) * 4);
                int4 qv3 = *(const int4*)(qs + qswz(u3) * 4);

                #define KP_BLOCK(JJ, SEL) {                                          \
                    int kp = c * 16 + q4 * 4 + (JJ);                                 \
                    const float* a0p = As + (2 * kp) * AS_STRIDE + mh8;              \
                    ulonglong2 A00 = *(const ulonglong2*)a0p;                        \
                    ulonglong2 A01 = *(const ulonglong2*)(a0p + 4);                  \
                    ulonglong2 A10 = *(const ulonglong2*)(a0p + AS_STRIDE);          \
                    ulonglong2 A11 = *(const ulonglong2*)(a0p + AS_STRIDE + 4);      \
                    BYTE_OP(qv0.SEL, cg4 + 0); BYTE_OP(qv1.SEL, cg4 + 1);            \
                    BYTE_OP(qv2.SEL, cg4 + 2); BYTE_OP(qv3.SEL, cg4 + 3); }
                KP_BLOCK(0, x) KP_BLOCK(1, y) KP_BLOCK(2, z) KP_BLOCK(3, w)
                #undef KP_BLOCK
            }
        }
    }

    // --- Fold scale + zeros/offset correction, store fp32 partials [k][n][m] ---
    #pragma unroll
    for (int j = 0; j < 8; j++) {
        int n  = nb + slot + 64 * j;
        int nc = n < N_DIM ? n : N_DIM - 1;
        float s = scales[(size_t)nc * NGROUPS + kidx];
        float z = zeros [(size_t)nc * NGROUPS + kidx];
        u64 czd = dupf(-(16.0f + z));
        u64 sd  = dupf(s);
        u64 o0 = acc[j][0], o1 = acc[j][1], o2 = acc[j][2], o3 = acc[j][3];
        fma2(o0, sumg[mhalf * 4 + 0], czd);
        fma2(o1, sumg[mhalf * 4 + 1], czd);
        fma2(o2, sumg[mhalf * 4 + 2], czd);
        fma2(o3, sumg[mhalf * 4 + 3], czd);
        o0 = mul2(o0, sd); o1 = mul2(o1, sd); o2 = mul2(o2, sd); o3 = mul2(o3, sd);
        if (n < N_DIM) {
            float* dst = g_scratch + ((size_t)kidx * N_DIM + n) * M_DIM + mh8;
            ulonglong2 v0; v0.x = o0; v0.y = o1;
            ulonglong2 v1; v1.x = o2; v1.y = o3;
            *(ulonglong2*)dst       = v0;
            *(ulonglong2*)(dst + 4) = v1;
        }
    }
}

__global__ void gptq_reduce(const float* __restrict__ bias, float* __restrict__ out) {
    int tid = blockIdx.x * blockDim.x + threadIdx.x;
    if (tid >= N_DIM * 2) return;
    int n = tid >> 1, h = tid & 1;
    float4 s0 = make_float4(0.f, 0.f, 0.f, 0.f);
    float4 s1 = make_float4(0.f, 0.f, 0.f, 0.f);
    const float* base = g_scratch + (size_t)n * M_DIM + h * 8;
    #pragma unroll
    for (int k = 0; k < KSPLIT; k++) {
        const float4* p = (const float4*)(base + (size_t)k * N_DIM * M_DIM);
        float4 a = p[0], b = p[1];
        s0.x += a.x; s0.y += a.y; s0.z += a.z; s0.w += a.w;
        s1.x += b.x; s1.y += b.y; s1.z += b.z; s1.w += b.w;
    }
    float bval = bias[n];
    int mb = 8 * h;
    out[(size_t)(mb + 0) * N_DIM + n] = s0.x + bval;
    out[(size_t)(mb + 1) * N_DIM + n] = s0.y + bval;
    out[(size_t)(mb + 2) * N_DIM + n] = s0.z + bval;
    out[(size_t)(mb + 3) * N_DIM + n] = s0.w + bval;
    out[(size_t)(mb + 4) * N_DIM + n] = s1.x + bval;
    out[(size_t)(mb + 5) * N_DIM + n] = s1.y + bval;
    out[(size_t)(mb + 6) * N_DIM + n] = s1.z + bval;
    out[(size_t)(mb + 7) * N_DIM + n] = s1.w + bval;
}

extern "C" void kernel_launch(void* const* d_in, const int* in_sizes, int n_in,
                              void* d_out, int out_size) {
    const float* A      = (const float*)d_in[0];
    const int*   qwv    = (const int*)  d_in[1];
    const float* scales = (const float*)d_in[2];
    const float* zeros  = (const float*)d_in[3];
    const float* bias   = (const float*)d_in[4];
    float* out = (float*)d_out;

    gptq_main<<<dim3(NBLKX, KSPLIT), THREADS>>>(A, qwv, scales, zeros);
    gptq_reduce<<<(N_DIM * 2 + 255) / 256, 256>>>(bias, out);
}

// round 5
// speedup vs baseline: 1.2284x; 1.0304x over previous
#include <cuda_runtime.h>
#include <cstdint>
#include <cstddef>

#define M_DIM   16
#define K_DIM   4096
#define N_DIM   11008
#define NGROUPS 32                 // K / 128
#define KINT    2048               // int32 per qweight row

#define THREADS  128
#define KSPLIT   16
#define KSEG     256               // k per CTA (2 quant groups)
#define SEG_INT  128               // ints per row per CTA
#define CTA_COLS 128
#define NBLKX    86                // 86*128 = 11008 exactly
#define NCHUNK   16
#define CHUNK_INT 8                // ints per row per chunk
#define QS_ROW   12                // padded ints per row (48B, 16B-aligned)
#define AS_F     36                // floats per kp row (144B, 16B-aligned)

typedef unsigned long long u64;

__device__ float g_scratch[(size_t)KSPLIT * N_DIM * M_DIM];   // [k][n][m]
__device__ int   g_cnt[NBLKX];

__device__ __forceinline__ void fma2(u64& d, u64 a, u64 b) {
    asm("fma.rn.f32x2 %0, %1, %2, %0;" : "+l"(d) : "l"(a), "l"(b));
}
__device__ __forceinline__ void add2(u64& d, u64 a) {
    asm("add.rn.f32x2 %0, %0, %1;" : "+l"(d) : "l"(a));
}
__device__ __forceinline__ u64 mul2(u64 a, u64 b) {
    u64 r; asm("mul.rn.f32x2 %0, %1, %2;" : "=l"(r) : "l"(a), "l"(b)); return r;
}
__device__ __forceinline__ u64 pairu(unsigned lo, unsigned hi) {
    u64 v; asm("mov.b64 %0, {%1, %2};" : "=l"(v) : "r"(lo), "r"(hi)); return v;
}
__device__ __forceinline__ u64 dupf(float f) {
    u64 v; asm("mov.b64 %0, {%1, %1};" : "=l"(v) : "f"(f)); return v;
}
__device__ __forceinline__ void unpack2(u64 v, float& lo, float& hi) {
    asm("mov.b64 {%0, %1}, %2;" : "=f"(lo), "=f"(hi) : "l"(v));
}

__device__ __forceinline__ void cp16(uint32_t smem_dst, const void* gsrc) {
    asm volatile("cp.async.cg.shared.global [%0], [%1], 16;" :: "r"(smem_dst), "l"(gsrc));
}
__device__ __forceinline__ void cp_commit() {
    asm volatile("cp.async.commit_group;" ::: "memory");
}
template<int N>
__device__ __forceinline__ void cp_wait() {
    asm volatile("cp.async.wait_group %0;" :: "n"(N) : "memory");
}

__global__ __launch_bounds__(THREADS, 4)
void gptq_fused(const float* __restrict__ A,
                const int*   __restrict__ qw,
                const float* __restrict__ scales,
                const float* __restrict__ zeros,
                const float* __restrict__ bias,
                float*       __restrict__ out) {
    __shared__ __align__(16) float As2[128 * AS_F];            // 18 KB: (even,odd) A pairs
    __shared__ __align__(16) int   qs[2][CTA_COLS * QS_ROW];   // 12 KB: double-buffered
    __shared__ u64 sumg_s[2 * 16];                             // per-group A pair-sums
    __shared__ int s_ticket;

    const int t     = threadIdx.x;
    const int nblk  = blockIdx.x;
    const int kidx  = blockIdx.y;
    const int slot  = t >> 1;           // 0..63: column slot (2 cols each)
    const int mh    = t & 1;            // m-half: 0 -> m 0-7, 1 -> m 8-15
    const int mh8   = mh * 8;
    const int kbase = kidx * KSEG;

    // --- Stage A as (even-k, odd-k) float2 pairs: As2[kp][m] ---
    #pragma unroll
    for (int i = 0; i < 16; i++) {
        int idx = t + i * THREADS;      // 2048 float2 loads
        int m   = idx >> 7;
        int kp  = idx & 127;
        float2 v = *(const float2*)(A + (size_t)m * K_DIM + kbase + 2 * kp);
        *(float2*)&As2[kp * AS_F + 2 * m] = v;
    }

    // --- Issue qweight chunks 0 and 1 (cp.async) ---
    const int row0 = slot;              // pass 0 rows 0..63, pass 1 rows 64..127
    const int h16  = (t & 1) * 4;       // int offset within chunk row
    #pragma unroll
    for (int c0 = 0; c0 < 2; c0++) {
        #pragma unroll
        for (int p = 0; p < 2; p++) {
            int row = p * 64 + row0;
            const int* src = qw + (size_t)(nblk * CTA_COLS + row) * KINT
                               + kidx * SEG_INT + c0 * CHUNK_INT + h16;
            uint32_t dst = (uint32_t)__cvta_generic_to_shared(
                &qs[c0][row * QS_ROW + h16]);
            cp16(dst, src);
        }
        cp_commit();
    }
    __syncthreads();

    // --- Per-group A pair-sums (for zeros/offset correction) ---
    if (t < 32) {
        int g = t >> 4, m = t & 15;
        u64 s = 0ull;
        #pragma unroll 4
        for (int kp = g * 64; kp < g * 64 + 64; kp++)
            add2(s, *(const u64*)&As2[kp * AS_F + 2 * m]);
        sumg_s[t] = s;
    }
    __syncthreads();

    u64   acc[2][8];                    // [col][m]: (even-k, odd-k) partials
    float ffold[2][8];                  // folded (scaled) results
    #pragma unroll
    for (int cc = 0; cc < 2; cc++)
        #pragma unroll
        for (int m = 0; m < 8; m++) { acc[cc][m] = 0ull; ffold[cc][m] = 0.0f; }

    for (int c = 0; c < NCHUNK; c++) {
        if (c == NCHUNK - 1) cp_wait<0>(); else cp_wait<1>();
        __syncthreads();

        const int* buf = qs[c & 1];
        #pragma unroll
        for (int q4 = 0; q4 < 2; q4++) {
            int4 qa4 = *(const int4*)&buf[slot * QS_ROW + q4 * 4];
            int4 qb4 = *(const int4*)&buf[(slot + 64) * QS_ROW + q4 * 4];
            int qa[4] = {qa4.x, qa4.y, qa4.z, qa4.w};
            int qb[4] = {qb4.x, qb4.y, qb4.z, qb4.w};
            #pragma unroll
            for (int b = 0; b < 4; b++) {
                const int kp = c * CHUNK_INT + q4 * 4 + b;
                const float* ap = As2 + kp * AS_F + 2 * mh8;
                ulonglong2 A0 = *(const ulonglong2*)(ap);
                ulonglong2 A1 = *(const ulonglong2*)(ap + 4);
                ulonglong2 A2 = *(const ulonglong2*)(ap + 8);
                ulonglong2 A3 = *(const ulonglong2*)(ap + 12);
                // w = (16+lo_nib, 16+hi_nib) via fp32 magic (no I2F)
                unsigned uqa = (unsigned)qa[b];
                u64 wa = pairu(((uqa << 19) & 0x00780000u) | 0x41800000u,
                               ((uqa << 15) & 0x00780000u) | 0x41800000u);
                fma2(acc[0][0], A0.x, wa); fma2(acc[0][1], A0.y, wa);
                fma2(acc[0][2], A1.x, wa); fma2(acc[0][3], A1.y, wa);
                fma2(acc[0][4], A2.x, wa); fma2(acc[0][5], A2.y, wa);
                fma2(acc[0][6], A3.x, wa); fma2(acc[0][7], A3.y, wa);
                unsigned uqb = (unsigned)qb[b];
                u64 wb = pairu(((uqb << 19) & 0x00780000u) | 0x41800000u,
                               ((uqb << 15) & 0x00780000u) | 0x41800000u);
                fma2(acc[1][0], A0.x, wb); fma2(acc[1][1], A0.y, wb);
                fma2(acc[1][2], A1.x, wb); fma2(acc[1][3], A1.y, wb);
                fma2(acc[1][4], A2.x, wb); fma2(acc[1][5], A2.y, wb);
                fma2(acc[1][6], A3.x, wb); fma2(acc[1][7], A3.y, wb);
            }
        }
        __syncthreads();

        // --- Fold at quant-group boundary: ffold += s*(acc - (16+z)*sumA) ---
        if ((c & 7) == 7) {
            const int g = c >> 3;
            #pragma unroll
            for (int cc = 0; cc < 2; cc++) {
                int n = nblk * CTA_COLS + slot + cc * 64;
                float s = scales[(size_t)n * NGROUPS + kidx * 2 + g];
                float z = zeros [(size_t)n * NGROUPS + kidx * 2 + g];
                u64 mz = dupf(-(16.0f + z));
                u64 sd = dupf(s);
                #pragma unroll
                for (int m = 0; m < 8; m++) {
                    u64 v = acc[cc][m];
                    fma2(v, sumg_s[g * 16 + mh8 + m], mz);
                    v = mul2(v, sd);
                    float lo, hi; unpack2(v, lo, hi);
                    ffold[cc][m] += lo + hi;
                    acc[cc][m] = 0ull;
                }
            }
        }

        // --- Issue chunk c+2 (writes the buffer just consumed; barrier above) ---
        if (c + 2 < NCHUNK) {
            #pragma unroll
            for (int p = 0; p < 2; p++) {
                int row = p * 64 + row0;
                const int* src = qw + (size_t)(nblk * CTA_COLS + row) * KINT
                                   + kidx * SEG_INT + (c + 2) * CHUNK_INT + h16;
                uint32_t dst = (uint32_t)__cvta_generic_to_shared(
                    &qs[c & 1][row * QS_ROW + h16]);
                cp16(dst, src);
            }
            cp_commit();
        }
    }

    // --- Store fp32 partials [k][n][m] ---
    #pragma unroll
    for (int cc = 0; cc < 2; cc++) {
        int n = nblk * CTA_COLS + slot + cc * 64;
        float* dst = g_scratch + ((size_t)kidx * N_DIM + n) * M_DIM + mh8;
        *(float4*)dst       = make_float4(ffold[cc][0], ffold[cc][1], ffold[cc][2], ffold[cc][3]);
        *(float4*)(dst + 4) = make_float4(ffold[cc][4], ffold[cc][5], ffold[cc][6], ffold[cc][7]);
    }

    // --- Last CTA per nblk reduces (deterministic k order) ---
    __threadfence();
    __syncthreads();
    if (t == 0) s_ticket = atomicAdd(&g_cnt[nblk], 1);
    __syncthreads();
    if (s_ticket == KSPLIT - 1) {
        if (t == 0) g_cnt[nblk] = 0;       // reset for next replay
        __threadfence();                    // acquire: see all partials
        const int mq = t >> 5, colb = t & 31;
        #pragma unroll
        for (int cs = 0; cs < 4; cs++) {
            int n = nblk * CTA_COLS + colb + cs * 32;
            float4 s = make_float4(0.f, 0.f, 0.f, 0.f);
            #pragma unroll
            for (int k = 0; k < KSPLIT; k++) {
                float4 v = *(const float4*)&g_scratch[((size_t)k * N_DIM + n) * M_DIM + mq * 4];
                s.x += v.x; s.y += v.y; s.z += v.z; s.w += v.w;
            }
            float bv = bias[n];
            out[(size_t)(mq * 4 + 0) * N_DIM + n] = s.x + bv;
            out[(size_t)(mq * 4 + 1) * N_DIM + n] = s.y + bv;
            out[(size_t)(mq * 4 + 2) * N_DIM + n] = s.z + bv;
            out[(size_t)(mq * 4 + 3) * N_DIM + n] = s.w + bv;
        }
    }
}

extern "C" void kernel_launch(void* const* d_in, const int* in_sizes, int n_in,
                              void* d_out, int out_size) {
    const float* A      = (const float*)d_in[0];
    const int*   qwv    = (const int*)  d_in[1];
    const float* scales = (const float*)d_in[2];
    const float* zeros  = (const float*)d_in[3];
    const float* bias   = (const float*)d_in[4];
    float* out = (float*)d_out;

    gptq_fused<<<dim3(NBLKX, KSPLIT), THREADS>>>(A, qwv, scales, zeros, bias, out);
}

// round 10
// speedup vs baseline: 1.7522x; 1.4265x over previous
#include <cuda_runtime.h>
#include <cuda_fp16.h>
#include <cstdint>
#include <cstddef>

#define M_DIM   16
#define K_DIM   4096
#define N_DIM   11008
#define NGROUPS 32
#define KINT    2048              // int32 per qweight row (1 byte payload each)

#define THREADS  256              // 8 warps x 32 cols
#define NT       43               // 43*256 = 11008
#define CTA_COLS 256
#define KSPLIT   8
#define KSEG     512
#define SEG_INT  256
#define NSTEP    32               // k16 steps per CTA
#define AS_H     520              // padded fp16 per A row (512+8)

__device__ float g_scratch[(size_t)KSPLIT * N_DIM * M_DIM];   // [k][n][m]
__device__ int   g_cnt[NT];

__device__ __forceinline__ uint32_t s2u(const void* p) {
    uint32_t a;
    asm("{ .reg .u64 t; cvta.to.shared.u64 t, %1; cvt.u32.u64 %0, t; }" : "=r"(a) : "l"(p));
    return a;
}
__device__ __forceinline__ uint32_t h2bits(__half2 h) {
    return *reinterpret_cast<uint32_t*>(&h);
}
// packed byte q -> fp16x2 scaled weights, single-rounding (bit-exact vs ref when z=0)
__device__ __forceinline__ uint32_t dq(uint32_t q, uint32_t s2, uint32_t c2) {
    uint32_t w = 0x4C004C00u | ((q << 6) & 0x000003C0u) | ((q << 18) & 0x03C00000u);
    uint32_t r;
    asm("fma.rn.f16x2 %0, %1, %2, %3;" : "=r"(r) : "r"(w), "r"(s2), "r"(c2));
    return r;
}
#define MMA(C, A0, A1, A2, A3, B0, B1)                                         \
    asm volatile(                                                              \
        "mma.sync.aligned.m16n8k16.row.col.f32.f16.f16.f32 "                   \
        "{%0,%1,%2,%3}, {%4,%5,%6,%7}, {%8,%9}, {%0,%1,%2,%3};"                \
        : "+f"(C[0]), "+f"(C[1]), "+f"(C[2]), "+f"(C[3])                       \
        : "r"(A0), "r"(A1), "r"(A2), "r"(A3), "r"(B0), "r"(B1))

__global__ void __launch_bounds__(THREADS)
gptq_hmma(const float* __restrict__ A, const int* __restrict__ qw,
          const float* __restrict__ scales, const float* __restrict__ zeros,
          const float* __restrict__ bias, float* __restrict__ out) {
    __shared__ __align__(16) __half As[16 * AS_H];   // 16.6 KB
    __shared__ int s_ticket;

    const int t    = threadIdx.x;
    const int warp = t >> 5, lane = t & 31;
    const int tile = blockIdx.x;
    const int kidx = blockIdx.y;

    // --- Stage A fp16 [16 m][512 k] (pad 520) ---
    #pragma unroll
    for (int i = 0; i < 16; i++) {
        int idx = t + i * THREADS;            // 4096 float2
        int m   = idx >> 8;
        int kp  = idx & 255;
        float2 v = *(const float2*)(A + (size_t)m * K_DIM + kidx * KSEG + 2 * kp);
        *(__half2*)&As[m * AS_H + 2 * kp] = __floats2half2_rn(v.x, v.y);
    }
    __syncthreads();

    const int nb   = tile * CTA_COLS + warp * 32;
    const int colq = lane >> 2;               // column within n8 tile
    const int kq   = lane & 3;                // k-quad selector

    const int* rp[4];
    size_t soff[4];
    #pragma unroll
    for (int j = 0; j < 4; j++) {
        int n   = nb + j * 8 + colq;
        rp[j]   = qw + (size_t)n * KINT + kidx * SEG_INT + kq;
        soff[j] = (size_t)n * NGROUPS + kidx * 4;
    }

    // --- Preload group-0 scale/zero raw; prefetch step-0 q ints ---
    float scn[4], zzn[4];
    #pragma unroll
    for (int j = 0; j < 4; j++) { scn[j] = scales[soff[j]]; zzn[j] = zeros[soff[j]]; }
    uint32_t q0[4], q1[4];
    #pragma unroll
    for (int j = 0; j < 4; j++) { q0[j] = (uint32_t)rp[j][0]; q1[j] = (uint32_t)rp[j][4]; }

    float c[4][4];
    #pragma unroll
    for (int j = 0; j < 4; j++)
        #pragma unroll
        for (int p = 0; p < 4; p++) c[j][p] = 0.0f;

    uint32_t s2[4], c2[4];
    const uint32_t abase = s2u(As) + ((lane & 15) * AS_H + (lane >> 4) * 8) * 2;

    #pragma unroll 4
    for (int s = 0; s < NSTEP; s++) {
        if ((s & 7) == 0) {                   // new quant group (k128)
            #pragma unroll
            for (int j = 0; j < 4; j++) {
                s2[j] = h2bits(__float2half2_rn(scn[j]));
                c2[j] = h2bits(__float2half2_rn(-(16.0f + zzn[j]) * scn[j]));
            }
            int g = s >> 3;
            if (g < 3) {                      // prefetch next group's raw s,z
                #pragma unroll
                for (int j = 0; j < 4; j++) {
                    scn[j] = scales[soff[j] + g + 1];
                    zzn[j] = zeros [soff[j] + g + 1];
                }
            }
        }

        uint32_t a0, a1, a2, a3;
        asm volatile("ldmatrix.sync.aligned.m8n8.x4.shared.b16 {%0,%1,%2,%3}, [%4];"
                     : "=r"(a0), "=r"(a1), "=r"(a2), "=r"(a3)
                     : "r"(abase + s * 32));

        uint32_t cq0[4], cq1[4];
        #pragma unroll
        for (int j = 0; j < 4; j++) { cq0[j] = q0[j]; cq1[j] = q1[j]; }
        if (s < NSTEP - 1) {                  // prefetch next step's q ints
            #pragma unroll
            for (int j = 0; j < 4; j++) {
                q0[j] = (uint32_t)rp[j][(s + 1) * 8];
                q1[j] = (uint32_t)rp[j][(s + 1) * 8 + 4];
            }
        }

        #pragma unroll
        for (int j = 0; j < 4; j++) {
            uint32_t b0 = dq(cq0[j], s2[j], c2[j]);
            uint32_t b1 = dq(cq1[j], s2[j], c2[j]);
            MMA(c[j], a0, a1, a2, a3, b0, b1);
        }
    }

    // --- Store fp32 partials [kidx][n][m] ---
    #pragma unroll
    for (int j = 0; j < 4; j++) {
        int n0 = nb + j * 8 + 2 * kq;         // D cols = 2*(lane&3), +1
        int m0 = colq;                        // D rows = lane>>2, +8
        float* base = g_scratch + ((size_t)kidx * N_DIM + n0) * M_DIM;
        base[m0]              = c[j][0];
        base[M_DIM + m0]      = c[j][1];
        base[m0 + 8]          = c[j][2];
        base[M_DIM + m0 + 8]  = c[j][3];
    }

    // --- Ticket: last CTA of this tile reduces (deterministic k order) ---
    __threadfence();
    __syncthreads();
    if (t == 0) s_ticket = atomicAdd(&g_cnt[tile], 1);
    __syncthreads();
    if (s_ticket == KSPLIT - 1) {
        if (t == 0) g_cnt[tile] = 0;          // reset for next graph replay
        __threadfence();                       // acquire all partials
        int n = tile * CTA_COLS + t;
        float4 a0 = make_float4(0.f, 0.f, 0.f, 0.f), a1 = a0, a2 = a0, a3 = a0;
        #pragma unroll
        for (int kk = 0; kk < KSPLIT; kk++) {
            const float4* p = (const float4*)(g_scratch + ((size_t)kk * N_DIM + n) * M_DIM);
            float4 v0 = p[0], v1 = p[1], v2 = p[2], v3 = p[3];
            a0.x += v0.x; a0.y += v0.y; a0.z += v0.z; a0.w += v0.w;
            a1.x += v1.x; a1.y += v1.y; a1.z += v1.z; a1.w += v1.w;
            a2.x += v2.x; a2.y += v2.y; a2.z += v2.z; a2.w += v2.w;
            a3.x += v3.x; a3.y += v3.y; a3.z += v3.z; a3.w += v3.w;
        }
        float bv = bias[n];
        float r[16] = {a0.x, a0.y, a0.z, a0.w, a1.x, a1.y, a1.z, a1.w,
                       a2.x, a2.y, a2.z, a2.w, a3.x, a3.y, a3.z, a3.w};
        #pragma unroll
        for (int m = 0; m < 16; m++)
            out[(size_t)m * N_DIM + n] = r[m] + bv;
    }
}

extern "C" void kernel_launch(void* const* d_in, const int* in_sizes, int n_in,
                              void* d_out, int out_size) {
    const float* A      = (const float*)d_in[0];
    const int*   qwv    = (const int*)  d_in[1];
    const float* scales = (const float*)d_in[2];
    const float* zeros  = (const float*)d_in[3];
    const float* bias   = (const float*)d_in[4];
    float* out = (float*)d_out;

    gptq_hmma<<<dim3(NT, KSPLIT), THREADS>>>(A, qwv, scales, zeros, bias, out);
}

// round 11
// speedup vs baseline: 2.3340x; 1.3320x over previous
#include <cuda_runtime.h>
#include <cuda_fp16.h>
#include <cstdint>
#include <cstddef>

#define M_DIM   16
#define K_DIM   4096
#define N_DIM   11008
#define NGROUPS 32
#define KINT    2048              // int32 per qweight row (1 byte payload each)

#define THREADS  256              // 8 warps x 32 cols
#define NT       43               // 43*256 = 11008
#define CTA_COLS 256
#define KSPLIT   8
#define KSEG     512
#define SEG_INT  256
#define NCH      8                // chunks per CTA
#define CH_INT   32               // ints per row per chunk (128 B)
#define AS_H     520              // padded fp16 per A row (512+8)

// dynamic smem: A tile + 2 qweight chunk buffers
#define SM_A   0                  // 16*520*2 = 16640 B
#define SM_Q0  16640              // 256 rows * 128 B = 32768 B
#define SM_Q1  (16640 + 32768)
#define SM_TOT (16640 + 2 * 32768)

__device__ float g_scratch[(size_t)KSPLIT * N_DIM * M_DIM];   // [k][n][m]
__device__ int   g_cnt[NT];

extern __shared__ __align__(1024) unsigned char smem_dyn[];

__device__ __forceinline__ uint32_t s2u(const void* p) {
    uint32_t a;
    asm("{ .reg .u64 t; cvta.to.shared.u64 t, %1; cvt.u32.u64 %0, t; }" : "=r"(a) : "l"(p));
    return a;
}
__device__ __forceinline__ void cp16(uint32_t d, const void* s) {
    asm volatile("cp.async.cg.shared.global [%0], [%1], 16;" :: "r"(d), "l"(s));
}
__device__ __forceinline__ void cp_commit() {
    asm volatile("cp.async.commit_group;" ::: "memory");
}
template<int N> __device__ __forceinline__ void cp_wait() {
    asm volatile("cp.async.wait_group %0;" :: "n"(N) : "memory");
}
__device__ __forceinline__ uint32_t h2bits(__half2 h) {
    return *reinterpret_cast<uint32_t*>(&h);
}
// packed byte q -> fp16x2 scaled weights, single-rounding (matches ref fp16 W for z=0)
__device__ __forceinline__ uint32_t dq(uint32_t q, uint32_t s2, uint32_t c2) {
    uint32_t w = 0x4C004C00u | ((q << 6) & 0x000003C0u) | ((q << 18) & 0x03C00000u);
    uint32_t r;
    asm("fma.rn.f16x2 %0, %1, %2, %3;" : "=r"(r) : "r"(w), "r"(s2), "r"(c2));
    return r;
}
#define MMA(C, A0, A1, A2, A3, B0, B1)                                         \
    asm volatile(                                                              \
        "mma.sync.aligned.m16n8k16.row.col.f32.f16.f16.f32 "                   \
        "{%0,%1,%2,%3}, {%4,%5,%6,%7}, {%8,%9}, {%0,%1,%2,%3};"                \
        : "+f"(C[0]), "+f"(C[1]), "+f"(C[2]), "+f"(C[3])                       \
        : "r"(A0), "r"(A1), "r"(A2), "r"(A3), "r"(B0), "r"(B1))

// stage one qweight chunk (256 rows x 128 B) via cp.async, swizzled
__device__ __forceinline__ void stage_chunk(const int* qw, int tile, int kidx,
                                            int ch, uint32_t qb_u32, int t) {
    const int rsub = t >> 3;          // 0..31
    const int seg  = t & 7;           // 16B segment within 128B row chunk
    #pragma unroll
    for (int i = 0; i < 8; i++) {
        int row = i * 32 + rsub;
        const int* src = qw + (size_t)(tile * CTA_COLS + row) * KINT
                       + kidx * SEG_INT + ch * CH_INT + seg * 4;
        uint32_t dst = qb_u32 + row * 128 + ((seg ^ (row & 7)) << 4);
        cp16(dst, src);
    }
    cp_commit();
}

__global__ void __launch_bounds__(THREADS)
gptq_hmma(const float* __restrict__ A, const int* __restrict__ qw,
          const float* __restrict__ scales, const float* __restrict__ zeros,
          const float* __restrict__ bias, float* __restrict__ out) {
    __shared__ int s_ticket;

    const int t    = threadIdx.x;
    const int warp = t >> 5, lane = t & 31;
    const int tile = blockIdx.x;
    const int kidx = blockIdx.y;

    __half* As = (__half*)(smem_dyn + SM_A);
    const uint32_t qb0 = s2u(smem_dyn + SM_Q0);
    const uint32_t qb1 = s2u(smem_dyn + SM_Q1);

    // --- Kick off qweight chunks 0,1 immediately ---
    stage_chunk(qw, tile, kidx, 0, qb0, t);
    stage_chunk(qw, tile, kidx, 1, qb1, t);

    // --- Stage A fp16 [16 m][512 k] (pad 520) ---
    #pragma unroll
    for (int i = 0; i < 16; i++) {
        int idx = t + i * THREADS;            // 4096 float2
        int m   = idx >> 8;
        int kp  = idx & 255;
        float2 v = *(const float2*)(A + (size_t)m * K_DIM + kidx * KSEG + 2 * kp);
        *(__half2*)&As[m * AS_H + 2 * kp] = __floats2half2_rn(v.x, v.y);
    }

    const int nb   = tile * CTA_COLS + warp * 32;
    const int colq = lane >> 2;               // 0..7: n within n8 tile / row group
    const int kq   = lane & 3;                // k-quad selector
    const int xorw = colq << 2;               // LDS swizzle term (4*(row&7))

    size_t soff[4];
    #pragma unroll
    for (int j = 0; j < 4; j++)
        soff[j] = (size_t)(nb + j * 8 + colq) * NGROUPS + kidx * 4;

    // per-j smem word base for this thread's q row (row = warp*32 + j*8 + colq)
    const uint32_t* qword0 = (const uint32_t*)(smem_dyn + SM_Q0);
    const uint32_t* qword1 = (const uint32_t*)(smem_dyn + SM_Q1);
    int rbase[4];
    #pragma unroll
    for (int j = 0; j < 4; j++) rbase[j] = (warp * 32 + j * 8 + colq) * 32;

    float scn[4], zzn[4];
    #pragma unroll
    for (int j = 0; j < 4; j++) { scn[j] = scales[soff[j]]; zzn[j] = zeros[soff[j]]; }

    float c[4][4];
    #pragma unroll
    for (int j = 0; j < 4; j++)
        #pragma unroll
        for (int p = 0; p < 4; p++) c[j][p] = 0.0f;

    uint32_t s2[4], c2[4];
    const uint32_t abase = s2u(As) + ((lane & 15) * AS_H + (lane >> 4) * 8) * 2;

    for (int ch = 0; ch < NCH; ch++) {
        if (ch == NCH - 1) cp_wait<0>(); else cp_wait<1>();
        __syncthreads();

        if ((ch & 1) == 0) {                  // new quant group (2 chunks = 128 k)
            #pragma unroll
            for (int j = 0; j < 4; j++) {
                s2[j] = h2bits(__float2half2_rn(scn[j]));
                c2[j] = h2bits(__float2half2_rn(-(16.0f + zzn[j]) * scn[j]));
            }
            int g = ch >> 1;
            if (g < 3) {
                #pragma unroll
                for (int j = 0; j < 4; j++) {
                    scn[j] = scales[soff[j] + g + 1];
                    zzn[j] = zeros [soff[j] + g + 1];
                }
            }
        }

        const uint32_t* qb = (ch & 1) ? qword1 : qword0;
        #pragma unroll
        for (int ls = 0; ls < 4; ls++) {
            const int s = ch * 4 + ls;
            uint32_t a0, a1, a2, a3;
            asm volatile("ldmatrix.sync.aligned.m8n8.x4.shared.b16 {%0,%1,%2,%3}, [%4];"
                         : "=r"(a0), "=r"(a1), "=r"(a2), "=r"(a3)
                         : "r"(abase + s * 32));
            const int w0 = (8 * ls + kq) ^ xorw;
            const int w1 = (8 * ls + 4 + kq) ^ xorw;
            uint32_t q0[4], q1[4];
            #pragma unroll
            for (int j = 0; j < 4; j++) {
                q0[j] = qb[rbase[j] + w0];
                q1[j] = qb[rbase[j] + w1];
            }
            #pragma unroll
            for (int j = 0; j < 4; j++) {
                uint32_t b0 = dq(q0[j], s2[j], c2[j]);
                uint32_t b1 = dq(q1[j], s2[j], c2[j]);
                MMA(c[j], a0, a1, a2, a3, b0, b1);
            }
        }
        __syncthreads();                      // all reads done before refill

        if (ch + 2 < NCH)
            stage_chunk(qw, tile, kidx, ch + 2, (ch & 1) ? qb1 : qb0, t);
    }

    // --- Store fp32 partials [kidx][n][m] ---
    #pragma unroll
    for (int j = 0; j < 4; j++) {
        int n0 = nb + j * 8 + 2 * kq;         // D cols = 2*(lane&3), +1
        int m0 = colq;                        // D rows = lane>>2, +8
        float* base = g_scratch + ((size_t)kidx * N_DIM + n0) * M_DIM;
        base[m0]              = c[j][0];
        base[M_DIM + m0]      = c[j][1];
        base[m0 + 8]          = c[j][2];
        base[M_DIM + m0 + 8]  = c[j][3];
    }

    // --- Ticket: last CTA of this tile reduces (deterministic k order) ---
    __threadfence();
    __syncthreads();
    if (t == 0) s_ticket = atomicAdd(&g_cnt[tile], 1);
    __syncthreads();
    if (s_ticket == KSPLIT - 1) {
        if (t == 0) g_cnt[tile] = 0;          // reset for next graph replay
        __threadfence();                       // acquire all partials
        int n = tile * CTA_COLS + t;
        float4 a0 = make_float4(0.f, 0.f, 0.f, 0.f), a1 = a0, a2 = a0, a3 = a0;
        #pragma unroll
        for (int kk = 0; kk < KSPLIT; kk++) {
            const float4* p = (const float4*)(g_scratch + ((size_t)kk * N_DIM + n) * M_DIM);
            float4 v0 = p[0], v1 = p[1], v2 = p[2], v3 = p[3];
            a0.x += v0.x; a0.y += v0.y; a0.z += v0.z; a0.w += v0.w;
            a1.x += v1.x; a1.y += v1.y; a1.z += v1.z; a1.w += v1.w;
            a2.x += v2.x; a2.y += v2.y; a2.z += v2.z; a2.w += v2.w;
            a3.x += v3.x; a3.y += v3.y; a3.z += v3.z; a3.w += v3.w;
        }
        float bv = bias[n];
        float r[16] = {a0.x, a0.y, a0.z, a0.w, a1.x, a1.y, a1.z, a1.w,
                       a2.x, a2.y, a2.z, a2.w, a3.x, a3.y, a3.z, a3.w};
        #pragma unroll
        for (int m = 0; m < 16; m++)
            out[(size_t)m * N_DIM + n] = r[m] + bv;
    }
}

extern "C" void kernel_launch(void* const* d_in, const int* in_sizes, int n_in,
                              void* d_out, int out_size) {
    const float* A      = (const float*)d_in[0];
    const int*   qwv    = (const int*)  d_in[1];
    const float* scales = (const float*)d_in[2];
    const float* zeros  = (const float*)d_in[3];
    const float* bias   = (const float*)d_in[4];
    float* out = (float*)d_out;

    cudaFuncSetAttribute(gptq_hmma, cudaFuncAttributeMaxDynamicSharedMemorySize, SM_TOT);
    gptq_hmma<<<dim3(NT, KSPLIT), THREADS, SM_TOT>>>(A, qwv, scales, zeros, bias, out);
}